// round 2
// baseline (speedup 1.0000x reference)
#include <cuda_runtime.h>
#include <cuda_bf16.h>
#include <math.h>

#define Bb 4
#define Nn 256
#define Dd 128
#define NODES (Bb*Nn)
#define MAXN (1.0f - 4e-3f)

// ---------------- scratch (__device__ globals; allocation-free) ----------------
__device__ float g_h[NODES*Dd];        // h after HypLinear
__device__ float g_s[NODES];           // ||h||^2
__device__ float g_r[NODES*Dd];        // h @ W1b^T
__device__ float g_m2[NODES*Nn];       // w_ij * V_ij
__device__ float g_sup[NODES*16];      // per-jtile partial sums of w_ij * U_ij
__device__ float g_support[NODES*Dd];  // aggregated tangent

__device__ __forceinline__ float artanhf_c(float x) {
    x = fminf(fmaxf(x, -1.0f + 1e-7f), 1.0f - 1e-7f);
    return 0.5f * logf((1.0f + x) / (1.0f - x));
}

// deterministic 128-thread block reduction, result broadcast to all threads
__device__ __forceinline__ float blockReduceSum128(float v, float* sbuf) {
    #pragma unroll
    for (int o = 16; o > 0; o >>= 1) v += __shfl_down_sync(0xffffffffu, v, o);
    int w = threadIdx.x >> 5;
    if ((threadIdx.x & 31) == 0) sbuf[w] = v;
    __syncthreads();
    float r = sbuf[0] + sbuf[1] + sbuf[2] + sbuf[3];
    __syncthreads();
    return r;
}

// ======================= K1: HypLinear =======================
// h = proj(mobius_add(proj(mobius_matvec(W,x)), proj(expmap0(b_lin))))
// 128 threads/block, 8 nodes per block. W transposed in smem (pitch 129).
__global__ void k_hyplinear(const float* __restrict__ x, const float* __restrict__ W,
                            const float* __restrict__ b_lin) {
    extern __shared__ float dsm[];
    float* Wt  = dsm;            // 128*129
    float* xs  = dsm + 128*129;  // 128
    float* red = xs + 128;       // 4
    int t = threadIdx.x;

    for (int idx = t; idx < Dd*Dd; idx += 128) {
        int k = idx >> 7, m = idx & 127;
        Wt[m*129 + k] = W[idx];
    }
    // hyperbolic bias: proj(expmap0(b_lin))
    float bv = b_lin[t];
    __syncthreads();
    float bn2 = blockReduceSum128(bv*bv, red);
    float bn  = fmaxf(sqrtf(bn2), 1e-15f);
    float hb  = tanhf(bn) * bv / bn;
    float hbn2 = blockReduceSum128(hb*hb, red);
    float hbn  = fmaxf(sqrtf(hbn2), 1e-15f);
    if (hbn > MAXN) hb = hb / hbn * MAXN;
    float y2 = blockReduceSum128(hb*hb, red);  // fresh norm^2 of bias point

    for (int u = 0; u < 8; u++) {
        int node = blockIdx.x * 8 + u;
        __syncthreads();
        xs[t] = x[node*Dd + t];
        __syncthreads();
        float xv = xs[t];
        float xn2 = blockReduceSum128(xv*xv, red);
        float mx = 0.f;
        #pragma unroll 8
        for (int m = 0; m < Dd; m++) mx = fmaf(xs[m], Wt[m*129 + t], mx);
        float mxn2 = blockReduceSum128(mx*mx, red);
        float res;
        if (mxn2 == 0.0f) {
            res = 0.0f;
        } else {
            float xn  = fmaxf(sqrtf(xn2), 1e-15f);
            float mxn = fmaxf(sqrtf(mxn2), 1e-15f);
            float arg = mxn / xn * artanhf_c(xn);
            res = tanhf(arg) * mx / mxn;
        }
        // proj
        float rn2 = blockReduceSum128(res*res, red);
        float rn  = fmaxf(sqrtf(rn2), 1e-15f);
        if (rn > MAXN) res = res / rn * MAXN;
        // mobius_add(res, hb)
        float x2 = blockReduceSum128(res*res, red);
        float xy = blockReduceSum128(res*hb, red);
        float A  = 1.0f + 2.0f*xy + y2;
        float Bc = 1.0f - x2;
        float den = fmaxf(1.0f + 2.0f*xy + x2*y2, 1e-15f);
        float h = (A*res + Bc*hb) / den;
        // proj
        float hn2 = blockReduceSum128(h*h, red);
        float hn  = fmaxf(sqrtf(hn2), 1e-15f);
        if (hn > MAXN) h = h / hn * MAXN;
        float hs2 = blockReduceSum128(h*h, red);
        g_h[node*Dd + t] = h;
        if (t == 0) g_s[node] = hs2;
    }
}

// ======================= K2: R = H @ W1b^T =======================
// W1b = att_w1[:, Dd:2Dd], row stride 2*Dd
__global__ void k_linearR(const float* __restrict__ att_w1) {
    extern __shared__ float dsm[];
    float* Wt = dsm;            // 128*129
    float* hs = dsm + 128*129;  // 128
    int t = threadIdx.x;
    for (int idx = t; idx < Dd*Dd; idx += 128) {
        int k = idx >> 7, m = idx & 127;
        Wt[m*129 + k] = att_w1[k*(2*Dd) + Dd + m];
    }
    for (int u = 0; u < 8; u++) {
        int node = blockIdx.x * 8 + u;
        __syncthreads();
        hs[t] = g_h[node*Dd + t];
        __syncthreads();
        float r = 0.f;
        #pragma unroll 8
        for (int m = 0; m < Dd; m++) r = fmaf(hs[m], Wt[m*129 + t], r);
        g_r[node*Dd + t] = r;
    }
}

// ======================= K3: pairwise attention =======================
// One thread per (i,j) pair in a 16x16 tile. x_loc_ij = U*h_i + V*h_j.
__global__ void k_pair(const float* __restrict__ mask, const float* __restrict__ att_b1,
                       const float* __restrict__ att_w2, const float* __restrict__ att_b2) {
    __shared__ float hiT[Dd*17], hjT[Dd*17], riT[Dd*17], rjT[Dd*17];
    __shared__ float w2s[Dd], b1s[Dd];
    __shared__ float ssi[16], ssj[16];
    __shared__ float redsm[16*17];

    int b  = blockIdx.z;
    int i0 = blockIdx.y * 16;
    int j0 = blockIdx.x * 16;
    int base = b * Nn;
    int tid = threadIdx.x;   // 256

    for (int idx = tid; idx < 16*Dd; idx += 256) {
        int row = idx >> 7, k = idx & 127;
        hiT[k*17 + row] = g_h[(base + i0 + row)*Dd + k];
        hjT[k*17 + row] = g_h[(base + j0 + row)*Dd + k];
        riT[k*17 + row] = g_r[(base + i0 + row)*Dd + k];
        rjT[k*17 + row] = g_r[(base + j0 + row)*Dd + k];
    }
    if (tid < 16) { ssi[tid] = g_s[base + i0 + tid]; ssj[tid] = g_s[base + j0 + tid]; }
    if (tid >= 32 && tid < 160) { int k = tid - 32; w2s[k] = att_w2[k]; b1s[k] = att_b1[k]; }
    int ti = tid >> 4, tj = tid & 15;
    float mval = mask[(base + i0 + ti)*Nn + j0 + tj];
    float b2v  = __ldg(att_b2);
    __syncthreads();

    // gram
    float g = 0.f;
    #pragma unroll 8
    for (int k = 0; k < Dd; k++) g = fmaf(hiT[k*17 + ti], hjT[k*17 + tj], g);
    float si = ssi[ti], sj = ssj[tj];

    float A   = 1.0f - 2.0f*g + sj;
    float Bc  = 1.0f - si;
    float den = fmaxf(1.0f - 2.0f*g + si*sj, 1e-15f);
    float p = -A / den, q = Bc / den;
    float sn2 = fmaf(p*p, si, fmaf(2.0f*p*q, g, q*q*sj));
    float sn  = fmaxf(sqrtf(fmaxf(sn2, 0.0f)), 1e-15f);
    float fac = fmaxf(1.0f - si, 1e-15f) * artanhf_c(sn) / sn;
    float U = fac * p, V = fac * q;

    // attention: e = sum_k w2[k] * silu(b1[k] + U*r_i[k] + V*r_j[k])
    float e = 0.f;
    #pragma unroll 4
    for (int k = 0; k < Dd; k++) {
        float a = fmaf(U, riT[k*17 + ti], fmaf(V, rjT[k*17 + tj], b1s[k]));
        float s = __fdividef(a, 1.0f + __expf(-a));
        e = fmaf(w2s[k], s, e);
    }
    float w = __fdividef(1.0f, 1.0f + __expf(-(e + b2v))) * mval;

    g_m2[(base + i0 + ti)*Nn + j0 + tj] = w * V;

    // deterministic per-jtile partial of sum_j w*U
    redsm[ti*17 + tj] = w * U;
    __syncthreads();
    if (tj == 0) {
        float s = 0.f;
        #pragma unroll
        for (int x2i = 0; x2i < 16; x2i++) s += redsm[ti*17 + x2i];
        g_sup[(base + i0 + ti)*16 + blockIdx.x] = s;
    }
}

// ======================= K4: support = diag(su)*H + M2 @ H =======================
__global__ void k_agg() {
    __shared__ float ms[16*Nn];
    int b  = blockIdx.y;
    int i0 = blockIdx.x * 16;
    int base = b * Nn;
    int tid = threadIdx.x;  // 128 = channel k
    for (int idx = tid; idx < 16*Nn; idx += 128) {
        int r = idx >> 8, cc = idx & 255;
        ms[r*Nn + cc] = g_m2[(base + i0 + r)*Nn + cc];
    }
    __syncthreads();
    float acc[16];
    #pragma unroll
    for (int ti = 0; ti < 16; ti++) acc[ti] = 0.f;
    for (int j = 0; j < Nn; j++) {
        float hv = g_h[(base + j)*Dd + tid];
        #pragma unroll
        for (int ti = 0; ti < 16; ti++) acc[ti] = fmaf(ms[ti*Nn + j], hv, acc[ti]);
    }
    #pragma unroll
    for (int ti = 0; ti < 16; ti++) {
        int node = base + i0 + ti;
        float su = 0.f;
        #pragma unroll
        for (int jt = 0; jt < 16; jt++) su += g_sup[node*16 + jt];
        g_support[node*Dd + tid] = fmaf(su, g_h[node*Dd + tid], acc[ti]);
    }
}

// ======================= K5: node MLP + expmap + HypAct =======================
__global__ void k_mlp(const float* __restrict__ mlp_w1, const float* __restrict__ mlp_b1,
                      const float* __restrict__ mlp_w2, const float* __restrict__ mlp_b2,
                      float* __restrict__ out) {
    extern __shared__ float dsm[];
    float* W1t = dsm;                 // 128*129 (second half of mlp_w1)
    float* W2t = dsm + 128*129;       // 128*129
    float* vs  = W2t + 128*129;       // 128
    float* red = vs + 128;            // 4
    int t = threadIdx.x;
    for (int idx = t; idx < Dd*Dd; idx += 128) {
        int k = idx >> 7, m = idx & 127;
        W1t[m*129 + k] = mlp_w1[k*(2*Dd) + Dd + m];
        W2t[m*129 + k] = mlp_w2[idx];
    }
    float b1v = mlp_b1[t], b2v = mlp_b2[t];

    for (int u = 0; u < 8; u++) {
        int node = blockIdx.x * 8 + u;
        __syncthreads();
        vs[t] = g_support[node*Dd + t];
        __syncthreads();
        float a1 = b1v;
        #pragma unroll 8
        for (int m = 0; m < Dd; m++) a1 = fmaf(vs[m], W1t[m*129 + t], a1);
        float sa = a1 / (1.0f + __expf(-a1));   // silu
        __syncthreads();
        vs[t] = sa;
        __syncthreads();
        float o = b2v;
        #pragma unroll 8
        for (int m = 0; m < Dd; m++) o = fmaf(vs[m], W2t[m*129 + t], o);
        // o == final tangent support_t (x_self ~ 0 dropped)

        float hval = g_h[node*Dd + t];
        float si   = g_s[node];
        // expmap(o, h)
        float un2 = blockReduceSum128(o*o, red);
        float un  = fmaxf(sqrtf(un2), 1e-15f);
        float lam = 2.0f / fmaxf(1.0f - si, 1e-15f);
        float tt  = tanhf(0.5f * lam * un);
        float sec = tt * o / un;
        // mobius_add(h, sec)
        float y2 = blockReduceSum128(sec*sec, red);
        float xy = blockReduceSum128(hval*sec, red);
        float A   = 1.0f + 2.0f*xy + y2;
        float Bc  = 1.0f - si;
        float den = fmaxf(1.0f + 2.0f*xy + si*y2, 1e-15f);
        float ov  = (A*hval + Bc*sec) / den;
        // proj
        float on2 = blockReduceSum128(ov*ov, red);
        float on  = fmaxf(sqrtf(on2), 1e-15f);
        if (on > MAXN) ov = ov / on * MAXN;
        // HypAct: silu(logmap0(ov)) -> expmap0 -> proj
        float pn2 = blockReduceSum128(ov*ov, red);
        float pn  = fmaxf(sqrtf(pn2), 1e-15f);
        float xt  = artanhf_c(pn) * ov / pn;
        xt = xt / (1.0f + __expf(-xt));
        float un3 = blockReduceSum128(xt*xt, red);
        float u3n = fmaxf(sqrtf(un3), 1e-15f);
        float rv  = tanhf(u3n) * xt / u3n;
        float rn2 = blockReduceSum128(rv*rv, red);
        float rn  = fmaxf(sqrtf(rn2), 1e-15f);
        if (rn > MAXN) rv = rv / rn * MAXN;
        out[node*Dd + t] = rv;
    }
}

// ======================= launch =======================
extern "C" void kernel_launch(void* const* d_in, const int* in_sizes, int n_in,
                              void* d_out, int out_size) {
    const float* x      = (const float*)d_in[0];
    const float* mask   = (const float*)d_in[1];
    const float* W      = (const float*)d_in[2];
    const float* b_lin  = (const float*)d_in[3];
    const float* att_w1 = (const float*)d_in[4];
    const float* att_b1 = (const float*)d_in[5];
    const float* att_w2 = (const float*)d_in[6];
    const float* att_b2 = (const float*)d_in[7];
    const float* mlp_w1 = (const float*)d_in[8];
    const float* mlp_b1 = (const float*)d_in[9];
    const float* mlp_w2 = (const float*)d_in[10];
    const float* mlp_b2 = (const float*)d_in[11];
    float* out = (float*)d_out;

    const int smem1 = (128*129 + 128 + 4) * (int)sizeof(float);           // ~66.6 KB
    const int smem2 = (128*129 + 128) * (int)sizeof(float);               // ~66.5 KB
    const int smem5 = (2*128*129 + 128 + 4) * (int)sizeof(float);         // ~132.6 KB
    cudaFuncSetAttribute(k_hyplinear, cudaFuncAttributeMaxDynamicSharedMemorySize, smem1);
    cudaFuncSetAttribute(k_linearR,   cudaFuncAttributeMaxDynamicSharedMemorySize, smem2);
    cudaFuncSetAttribute(k_mlp,       cudaFuncAttributeMaxDynamicSharedMemorySize, smem5);

    k_hyplinear<<<NODES/8, 128, smem1>>>(x, W, b_lin);
    k_linearR<<<NODES/8, 128, smem2>>>(att_w1);
    dim3 g3(Nn/16, Nn/16, Bb);
    k_pair<<<g3, 256>>>(mask, att_b1, att_w2, att_b2);
    dim3 g4(Nn/16, Bb);
    k_agg<<<g4, 128>>>();
    k_mlp<<<NODES/8, 128, smem5>>>(mlp_w1, mlp_b1, mlp_w2, mlp_b2, out);
}

// round 4
// speedup vs baseline: 1.4468x; 1.4468x over previous
#include <cuda_runtime.h>
#include <cuda_bf16.h>
#include <math.h>

#define Bb 4
#define Nn 256
#define Dd 128
#define NODES (Bb*Nn)
#define MAXN (1.0f - 4e-3f)

// ---------------- scratch (__device__ globals; allocation-free) ----------------
__device__ float g_h[NODES*Dd];          // h after HypLinear
__device__ float g_s[NODES];             // ||h||^2
__device__ float g_r[NODES*Dd];          // h @ W1b^T
__device__ float g_m2[NODES*Nn];         // w_ij * V_ij
__device__ float g_sup[NODES*16];        // per-jtile partial sums of w_ij * U_ij
__device__ float g_part[4*NODES*Dd];     // j-split partials of M2 @ H

__device__ __forceinline__ float artanhf_c(float x) {
    x = fminf(fmaxf(x, -1.0f + 1e-7f), 1.0f - 1e-7f);
    return 0.5f * logf((1.0f + x) / (1.0f - x));
}

__device__ __forceinline__ float tanhap(float x) {
    float y;
    asm("tanh.approx.f32 %0, %1;" : "=f"(y) : "f"(x));
    return y;
}

// deterministic 128-thread block reduction, result broadcast to all threads
__device__ __forceinline__ float blockReduceSum128(float v, float* sbuf) {
    #pragma unroll
    for (int o = 16; o > 0; o >>= 1) v += __shfl_down_sync(0xffffffffu, v, o);
    int w = threadIdx.x >> 5;
    if ((threadIdx.x & 31) == 0) sbuf[w] = v;
    __syncthreads();
    float r = sbuf[0] + sbuf[1] + sbuf[2] + sbuf[3];
    __syncthreads();
    return r;
}

// ======================= K1: HypLinear + R = H @ W1b^T (fused) =======================
__global__ void k_hyplinear(const float* __restrict__ x, const float* __restrict__ W,
                            const float* __restrict__ b_lin, const float* __restrict__ att_w1) {
    extern __shared__ float dsm[];
    float* Wt  = dsm;                 // 128*129
    float* W1t = dsm + 128*129;       // 128*129
    float* xs  = W1t + 128*129;       // 128
    float* red = xs + 128;            // 4
    int t = threadIdx.x;

    for (int idx = t; idx < Dd*Dd; idx += 128) {
        int k = idx >> 7, m = idx & 127;
        Wt[m*129 + k]  = W[idx];
        W1t[m*129 + k] = att_w1[k*(2*Dd) + Dd + m];
    }
    // hyperbolic bias: proj(expmap0(b_lin))
    float bv = b_lin[t];
    __syncthreads();
    float bn2 = blockReduceSum128(bv*bv, red);
    float bn  = fmaxf(sqrtf(bn2), 1e-15f);
    float hb  = tanhf(bn) * bv / bn;
    float hbn = fminf(fabsf(tanhf(bn)), 1e30f);          // ||hb|| = |tanh(bn)|
    if (hbn > MAXN) hb = hb / hbn * MAXN;
    float y2 = (hbn > MAXN) ? MAXN*MAXN : hbn*hbn;

    for (int u = 0; u < 8; u++) {
        int node = blockIdx.x * 8 + u;
        __syncthreads();
        xs[t] = x[node*Dd + t];
        __syncthreads();
        float xv = xs[t];
        float xn2 = blockReduceSum128(xv*xv, red);
        float mx = 0.f;
        #pragma unroll 8
        for (int m = 0; m < Dd; m++) mx = fmaf(xs[m], Wt[m*129 + t], mx);
        float mxn2 = blockReduceSum128(mx*mx, red);
        float res; float rn;
        if (mxn2 == 0.0f) {
            res = 0.0f; rn = 0.0f;
        } else {
            float xn  = fmaxf(sqrtf(xn2), 1e-15f);
            float mxn = fmaxf(sqrtf(mxn2), 1e-15f);
            float arg = mxn / xn * artanhf_c(xn);
            float tt  = tanhf(arg);
            res = tt * mx / mxn;
            rn  = fabsf(tt);                              // ||res|| = |tanh(arg)|
        }
        // proj
        float rnc = fmaxf(rn, 1e-15f);
        if (rnc > MAXN) res = res / rnc * MAXN;
        float x2 = (rnc > MAXN) ? MAXN*MAXN : rn*rn;
        // mobius_add(res, hb)
        float xy = blockReduceSum128(res*hb, red);
        float A  = 1.0f + 2.0f*xy + y2;
        float Bc = 1.0f - x2;
        float den = fmaxf(1.0f + 2.0f*xy + x2*y2, 1e-15f);
        float h = (A*res + Bc*hb) / den;
        // proj
        float hn2 = blockReduceSum128(h*h, red);
        float hn  = fmaxf(sqrtf(hn2), 1e-15f);
        float hs2;
        if (hn > MAXN) { h = h / hn * MAXN; hs2 = MAXN*MAXN; }
        else           { hs2 = hn2; }
        g_h[node*Dd + t] = h;
        if (t == 0) g_s[node] = hs2;
        // fused R = h @ W1b^T
        __syncthreads();
        xs[t] = h;
        __syncthreads();
        float r = 0.f;
        #pragma unroll 8
        for (int m = 0; m < Dd; m++) r = fmaf(xs[m], W1t[m*129 + t], r);
        g_r[node*Dd + t] = r;
    }
}

// ======================= K3: pairwise attention =======================
// One thread per (i,j) pair in a 16x16 tile. x_loc_ij = U*h_i + V*h_j.
// Row-major float4 smem tiles, pitch 33 float4 (132 floats): i-indexed reads are
// broadcast; j-indexed reads are conflict-free per 8-lane phase (4*tj mod 32 distinct).
__global__ void k_pair(const float* __restrict__ mask, const float* __restrict__ att_b1,
                       const float* __restrict__ att_w2, const float* __restrict__ att_b2) {
    __shared__ float4 hi4[16*33], hj4[16*33], ri4[16*33], rj4[16*33];
    __shared__ float4 w2s4[32], b1s4[32];
    __shared__ float ssi[16], ssj[16];
    __shared__ float redsm[16*17];

    int b  = blockIdx.z;
    int i0 = blockIdx.y * 16;
    int j0 = blockIdx.x * 16;
    int base = b * Nn;
    int tid = threadIdx.x;   // 256

    for (int idx = tid; idx < 16*32; idx += 256) {
        int row = idx >> 5, k4 = idx & 31;
        hi4[row*33 + k4] = ((const float4*)(g_h + (base + i0 + row)*Dd))[k4];
        hj4[row*33 + k4] = ((const float4*)(g_h + (base + j0 + row)*Dd))[k4];
        ri4[row*33 + k4] = ((const float4*)(g_r + (base + i0 + row)*Dd))[k4];
        rj4[row*33 + k4] = ((const float4*)(g_r + (base + j0 + row)*Dd))[k4];
    }
    if (tid < 16) { ssi[tid] = g_s[base + i0 + tid]; ssj[tid] = g_s[base + j0 + tid]; }
    if (tid >= 64 && tid < 96)  w2s4[tid - 64] = ((const float4*)att_w2)[tid - 64];
    if (tid >= 96 && tid < 128) b1s4[tid - 96] = ((const float4*)att_b1)[tid - 96];
    int ti = tid >> 4, tj = tid & 15;
    float mval = mask[(base + i0 + ti)*Nn + j0 + tj];
    float b2v  = __ldg(att_b2);
    __syncthreads();

    // gram <h_i, h_j>
    float g = 0.f;
    #pragma unroll
    for (int k4 = 0; k4 < 32; k4++) {
        float4 a = hi4[ti*33 + k4];
        float4 c = hj4[tj*33 + k4];
        g = fmaf(a.x, c.x, fmaf(a.y, c.y, fmaf(a.z, c.z, fmaf(a.w, c.w, g))));
    }
    float si = ssi[ti], sj = ssj[tj];

    float A   = 1.0f - 2.0f*g + sj;
    float Bc  = 1.0f - si;
    float den = fmaxf(1.0f - 2.0f*g + si*sj, 1e-15f);
    float p = -A / den, q = Bc / den;
    float sn2 = fmaf(p*p, si, fmaf(2.0f*p*q, g, q*q*sj));
    float sn  = fmaxf(sqrtf(fmaxf(sn2, 0.0f)), 1e-15f);
    float fac = fmaxf(1.0f - si, 1e-15f) * artanhf_c(sn) / sn;
    float U = fac * p, V = fac * q;

    // attention logit: e = sum_k w2[k] * silu(b1[k] + U*r_i[k] + V*r_j[k])
    // silu(a) = 0.5*a*(1 + tanh(a/2)); tanh via 1 MUFU (tanh.approx.f32)
    float e = 0.f;
    #pragma unroll
    for (int k4 = 0; k4 < 32; k4++) {
        float4 rv = ri4[ti*33 + k4];
        float4 sv = rj4[tj*33 + k4];
        float4 bv = b1s4[k4];
        float4 wv = w2s4[k4];
        {
            float a = fmaf(U, rv.x, fmaf(V, sv.x, bv.x));
            float s = 0.5f * fmaf(a, tanhap(0.5f*a), a);
            e = fmaf(wv.x, s, e);
        }
        {
            float a = fmaf(U, rv.y, fmaf(V, sv.y, bv.y));
            float s = 0.5f * fmaf(a, tanhap(0.5f*a), a);
            e = fmaf(wv.y, s, e);
        }
        {
            float a = fmaf(U, rv.z, fmaf(V, sv.z, bv.z));
            float s = 0.5f * fmaf(a, tanhap(0.5f*a), a);
            e = fmaf(wv.z, s, e);
        }
        {
            float a = fmaf(U, rv.w, fmaf(V, sv.w, bv.w));
            float s = 0.5f * fmaf(a, tanhap(0.5f*a), a);
            e = fmaf(wv.w, s, e);
        }
    }
    // accurate final sigmoid (one per pair)
    float w = __fdividef(1.0f, 1.0f + __expf(-(e + b2v))) * mval;

    g_m2[(base + i0 + ti)*Nn + j0 + tj] = w * V;

    // deterministic per-jtile partial of sum_j w*U
    redsm[ti*17 + tj] = w * U;
    __syncthreads();
    if (tj == 0) {
        float s = 0.f;
        #pragma unroll
        for (int x2i = 0; x2i < 16; x2i++) s += redsm[ti*17 + x2i];
        g_sup[(base + i0 + ti)*16 + blockIdx.x] = s;
    }
}

// ======================= K4: j-split partials of M2 @ H =======================
// grid (16 i-tiles, 4 j-splits, 4 batches), block 128 (= channel)
__global__ void k_agg() {
    __shared__ float4 ms4[16*16];     // 16 rows x 64 j (as 16 float4)
    int b  = blockIdx.z;
    int js = blockIdx.y;
    int i0 = blockIdx.x * 16;
    int base = b * Nn;
    int j0 = js * 64;
    int tid = threadIdx.x;  // 128 = channel k

    for (int idx = tid; idx < 256; idx += 128) {
        int r = idx >> 4, k = idx & 15;
        ms4[r*16 + k] = ((const float4*)(g_m2 + (base + i0 + r)*Nn + j0))[k];
    }
    __syncthreads();
    float acc[16];
    #pragma unroll
    for (int ti = 0; ti < 16; ti++) acc[ti] = 0.f;
    #pragma unroll 4
    for (int j4 = 0; j4 < 16; j4++) {
        const float* hp = g_h + (base + j0 + j4*4)*Dd + tid;
        float h0 = hp[0], h1 = hp[Dd], h2 = hp[2*Dd], h3 = hp[3*Dd];
        #pragma unroll
        for (int ti = 0; ti < 16; ti++) {
            float4 m = ms4[ti*16 + j4];
            acc[ti] = fmaf(m.x, h0, fmaf(m.y, h1, fmaf(m.z, h2, fmaf(m.w, h3, acc[ti]))));
        }
    }
    #pragma unroll
    for (int ti = 0; ti < 16; ti++)
        g_part[(js*NODES + base + i0 + ti)*Dd + tid] = acc[ti];
}

// ======================= K5: combine + node MLP + expmap + HypAct =======================
__global__ void k_mlp(const float* __restrict__ mlp_w1, const float* __restrict__ mlp_b1,
                      const float* __restrict__ mlp_w2, const float* __restrict__ mlp_b2,
                      float* __restrict__ out) {
    extern __shared__ float dsm[];
    float* W1t = dsm;                 // 128*129 (second half of mlp_w1)
    float* W2t = dsm + 128*129;       // 128*129
    float* vs  = W2t + 128*129;       // 128
    float* red = vs + 128;            // 4
    int t = threadIdx.x;
    for (int idx = t; idx < Dd*Dd; idx += 128) {
        int k = idx >> 7, m = idx & 127;
        W1t[m*129 + k] = mlp_w1[k*(2*Dd) + Dd + m];
        W2t[m*129 + k] = mlp_w2[idx];
    }
    float b1v = mlp_b1[t], b2v = mlp_b2[t];

    for (int u = 0; u < 8; u++) {
        int node = blockIdx.x * 8 + u;
        // combine j-split partials + diagonal term
        float sv = 0.f;
        #pragma unroll
        for (int js = 0; js < 4; js++) sv += g_part[(js*NODES + node)*Dd + t];
        float su = 0.f;
        #pragma unroll
        for (int jt = 0; jt < 16; jt++) su += g_sup[node*16 + jt];
        float hval = g_h[node*Dd + t];
        float support = fmaf(su, hval, sv);
        __syncthreads();
        vs[t] = support;
        __syncthreads();
        float a1 = b1v;
        #pragma unroll 8
        for (int m = 0; m < Dd; m++) a1 = fmaf(vs[m], W1t[m*129 + t], a1);
        float sa = a1 / (1.0f + __expf(-a1));   // silu (accurate)
        __syncthreads();
        vs[t] = sa;
        __syncthreads();
        float o = b2v;
        #pragma unroll 8
        for (int m = 0; m < Dd; m++) o = fmaf(vs[m], W2t[m*129 + t], o);
        // o == final tangent support_t (x_self ~ 0 dropped)

        float si = g_s[node];
        // expmap(o, h)
        float un2 = blockReduceSum128(o*o, red);
        float un  = fmaxf(sqrtf(un2), 1e-15f);
        float lam = 2.0f / fmaxf(1.0f - si, 1e-15f);
        float tt  = tanhf(0.5f * lam * un);
        float sec = tt * o / un;
        float y2  = tt * tt;                    // ||sec||^2 analytically
        // mobius_add(h, sec)
        float xy = blockReduceSum128(hval*sec, red);
        float A   = 1.0f + 2.0f*xy + y2;
        float Bc  = 1.0f - si;
        float den = fmaxf(1.0f + 2.0f*xy + si*y2, 1e-15f);
        float ov  = (A*hval + Bc*sec) / den;
        // proj
        float on2 = blockReduceSum128(ov*ov, red);
        float on  = fmaxf(sqrtf(on2), 1e-15f);
        float pn2;
        if (on > MAXN) { ov = ov / on * MAXN; pn2 = MAXN*MAXN; }
        else           { pn2 = on2; }
        // HypAct: silu(logmap0(ov)) -> expmap0 -> proj
        float pn  = fmaxf(sqrtf(pn2), 1e-15f);
        float xt  = artanhf_c(pn) * ov / pn;
        xt = xt / (1.0f + __expf(-xt));
        float un3 = blockReduceSum128(xt*xt, red);
        float u3n = fmaxf(sqrtf(un3), 1e-15f);
        float t3  = tanhf(u3n);
        float rv  = t3 * xt / u3n;
        float rn  = fmaxf(fabsf(t3), 1e-15f);   // ||rv|| analytically
        if (rn > MAXN) rv = rv / rn * MAXN;
        out[node*Dd + t] = rv;
    }
}

// ======================= launch =======================
extern "C" void kernel_launch(void* const* d_in, const int* in_sizes, int n_in,
                              void* d_out, int out_size) {
    const float* x      = (const float*)d_in[0];
    const float* mask   = (const float*)d_in[1];
    const float* W      = (const float*)d_in[2];
    const float* b_lin  = (const float*)d_in[3];
    const float* att_w1 = (const float*)d_in[4];
    const float* att_b1 = (const float*)d_in[5];
    const float* att_w2 = (const float*)d_in[6];
    const float* att_b2 = (const float*)d_in[7];
    const float* mlp_w1 = (const float*)d_in[8];
    const float* mlp_b1 = (const float*)d_in[9];
    const float* mlp_w2 = (const float*)d_in[10];
    const float* mlp_b2 = (const float*)d_in[11];
    float* out = (float*)d_out;

    const int smem1 = (2*128*129 + 128 + 4) * (int)sizeof(float);   // ~132.6 KB
    const int smem5 = (2*128*129 + 128 + 4) * (int)sizeof(float);   // ~132.6 KB
    cudaFuncSetAttribute(k_hyplinear, cudaFuncAttributeMaxDynamicSharedMemorySize, smem1);
    cudaFuncSetAttribute(k_mlp,       cudaFuncAttributeMaxDynamicSharedMemorySize, smem5);

    k_hyplinear<<<NODES/8, 128, smem1>>>(x, W, b_lin, att_w1);
    dim3 g3(Nn/16, Nn/16, Bb);
    k_pair<<<g3, 256>>>(mask, att_b1, att_w2, att_b2);
    dim3 g4(Nn/16, 4, Bb);
    k_agg<<<g4, 128>>>();
    k_mlp<<<NODES/8, 128, smem5>>>(mlp_w1, mlp_b1, mlp_w2, mlp_b2, out);
}

// round 5
// speedup vs baseline: 2.3955x; 1.6557x over previous
#include <cuda_runtime.h>
#include <cuda_bf16.h>
#include <math.h>

#define Bb 4
#define Nn 256
#define Dd 128
#define NODES (Bb*Nn)
#define MAXN (1.0f - 4e-3f)
#define WP 33   // weight smem pitch in float4 (132 floats)

// ---------------- scratch (__device__ globals; allocation-free) ----------------
__device__ float g_h[NODES*Dd];          // h after HypLinear
__device__ float g_s[NODES];             // ||h||^2
__device__ float g_r[NODES*Dd];          // h @ W1b^T
__device__ float g_m2[NODES*Nn];         // w_ij * V_ij
__device__ float g_sup[NODES*16];        // per-jtile partial sums of w_ij * U_ij
__device__ float g_part[4*NODES*Dd];     // j-split partials of M2 @ H

__device__ __forceinline__ float artanhf_c(float x) {
    x = fminf(fmaxf(x, -1.0f + 1e-7f), 1.0f - 1e-7f);
    return 0.5f * logf((1.0f + x) / (1.0f - x));
}

__device__ __forceinline__ float tanhap(float x) {
    float y;
    asm("tanh.approx.f32 %0, %1;" : "=f"(y) : "f"(x));
    return y;
}

__device__ __forceinline__ float dot4(float4 a, float4 b) {
    return fmaf(a.x, b.x, fmaf(a.y, b.y, fmaf(a.z, b.z, a.w * b.w)));
}

// deterministic warp-wide sum, broadcast to all lanes (fixed butterfly order)
__device__ __forceinline__ float warpSum(float v) {
    #pragma unroll
    for (int o = 16; o > 0; o >>= 1) v += __shfl_xor_sync(0xffffffffu, v, o);
    return v;
}

// 128x128 matvec: out channels c=4*lane..4*lane+3; Wt pitch WP float4, v = 32 float4
__device__ __forceinline__ float4 matvec128(const float4* __restrict__ Wt,
                                            const float4* __restrict__ v, int lane) {
    float4 a = make_float4(0.f, 0.f, 0.f, 0.f);
    #pragma unroll 8
    for (int m4 = 0; m4 < 32; m4++) {
        float4 vm = v[m4];
        const float4* wr = Wt + (m4*4)*WP + lane;
        float4 w;
        w = wr[0];
        a.x = fmaf(vm.x, w.x, a.x); a.y = fmaf(vm.x, w.y, a.y);
        a.z = fmaf(vm.x, w.z, a.z); a.w = fmaf(vm.x, w.w, a.w);
        w = wr[WP];
        a.x = fmaf(vm.y, w.x, a.x); a.y = fmaf(vm.y, w.y, a.y);
        a.z = fmaf(vm.y, w.z, a.z); a.w = fmaf(vm.y, w.w, a.w);
        w = wr[2*WP];
        a.x = fmaf(vm.z, w.x, a.x); a.y = fmaf(vm.z, w.y, a.y);
        a.z = fmaf(vm.z, w.z, a.z); a.w = fmaf(vm.z, w.w, a.w);
        w = wr[3*WP];
        a.x = fmaf(vm.w, w.x, a.x); a.y = fmaf(vm.w, w.y, a.y);
        a.z = fmaf(vm.w, w.z, a.z); a.w = fmaf(vm.w, w.w, a.w);
    }
    return a;
}

// ======================= K1: HypLinear + R = H @ W1b^T (warp-per-node) =======================
// 256 threads = 8 warps, 1 node/warp, grid 128.
__global__ void k_hyplinear(const float* __restrict__ x, const float* __restrict__ W,
                            const float* __restrict__ b_lin, const float* __restrict__ att_w1) {
    extern __shared__ float4 dsm4[];
    float4* Ws4  = dsm4;              // 128*WP
    float4* W1s4 = dsm4 + 128*WP;     // 128*WP
    float4* vs4  = W1s4 + 128*WP;     // 8*32
    float* Ws  = (float*)Ws4;
    float* W1s = (float*)W1s4;
    int t = threadIdx.x, wid = t >> 5, lane = t & 31;

    for (int idx = t; idx < Dd*Dd; idx += 256) {
        int c = idx >> 7, m = idx & 127;
        Ws[m*132 + c]  = W[c*Dd + m];
        W1s[m*132 + c] = att_w1[c*(2*Dd) + Dd + m];
    }
    // hyperbolic bias: proj(expmap0(b_lin)) — per-warp redundant, cheap
    float4 bv = ((const float4*)b_lin)[lane];
    float bn2 = warpSum(dot4(bv, bv));
    float bn  = fmaxf(sqrtf(bn2), 1e-15f);
    float tb  = tanhf(bn);
    float4 hb = make_float4(tb*bv.x/bn, tb*bv.y/bn, tb*bv.z/bn, tb*bv.w/bn);
    float hbn = fabsf(tb);
    if (hbn > MAXN) { float s = MAXN/hbn; hb.x*=s; hb.y*=s; hb.z*=s; hb.w*=s; }
    float y2 = (hbn > MAXN) ? MAXN*MAXN : hbn*hbn;
    __syncthreads();

    int node = blockIdx.x * 8 + wid;
    float4* vw = vs4 + wid*32;

    float4 x4 = ((const float4*)(x + node*Dd))[lane];
    vw[lane] = x4;
    __syncwarp();
    float xn2 = warpSum(dot4(x4, x4));
    float4 mx = matvec128(Ws4, vw, lane);
    float mxn2 = warpSum(dot4(mx, mx));
    float4 res; float rn;
    if (mxn2 == 0.0f) {
        res = make_float4(0.f,0.f,0.f,0.f); rn = 0.0f;
    } else {
        float xn  = fmaxf(sqrtf(xn2), 1e-15f);
        float mxn = fmaxf(sqrtf(mxn2), 1e-15f);
        float arg = mxn / xn * artanhf_c(xn);
        float tt  = tanhf(arg);
        float sc  = tt / mxn;
        res = make_float4(sc*mx.x, sc*mx.y, sc*mx.z, sc*mx.w);
        rn  = fabsf(tt);
    }
    // proj (analytic norm)
    float rnc = fmaxf(rn, 1e-15f);
    if (rnc > MAXN) { float s = MAXN/rnc; res.x*=s; res.y*=s; res.z*=s; res.w*=s; }
    float x2 = (rnc > MAXN) ? MAXN*MAXN : rn*rn;
    // mobius_add(res, hb)
    float xy = warpSum(dot4(res, hb));
    float A  = 1.0f + 2.0f*xy + y2;
    float Bc = 1.0f - x2;
    float den = fmaxf(1.0f + 2.0f*xy + x2*y2, 1e-15f);
    float id = 1.0f/den;
    float4 h = make_float4((A*res.x + Bc*hb.x)*id, (A*res.y + Bc*hb.y)*id,
                           (A*res.z + Bc*hb.z)*id, (A*res.w + Bc*hb.w)*id);
    // proj
    float hn2 = warpSum(dot4(h, h));
    float hn  = fmaxf(sqrtf(hn2), 1e-15f);
    float hs2;
    if (hn > MAXN) { float s = MAXN/hn; h.x*=s; h.y*=s; h.z*=s; h.w*=s; hs2 = MAXN*MAXN; }
    else           { hs2 = hn2; }
    ((float4*)(g_h + node*Dd))[lane] = h;
    if (lane == 0) g_s[node] = hs2;
    // fused R = h @ W1b^T
    __syncwarp();               // all lanes done reading vw (x)
    vw[lane] = h;
    __syncwarp();
    float4 r = matvec128(W1s4, vw, lane);
    ((float4*)(g_r + node*Dd))[lane] = r;
}

// ======================= K3: pairwise attention =======================
// One thread per (i,j) pair in a 16x16 tile. x_loc_ij = U*h_i + V*h_j.
__global__ void k_pair(const float* __restrict__ mask, const float* __restrict__ att_b1,
                       const float* __restrict__ att_w2, const float* __restrict__ att_b2) {
    __shared__ float4 hi4[16*33], hj4[16*33], ri4[16*33], rj4[16*33];
    __shared__ float4 w2s4[32], b1s4[32];
    __shared__ float ssi[16], ssj[16];
    __shared__ float redsm[16*17];

    int b  = blockIdx.z;
    int i0 = blockIdx.y * 16;
    int j0 = blockIdx.x * 16;
    int base = b * Nn;
    int tid = threadIdx.x;   // 256

    for (int idx = tid; idx < 16*32; idx += 256) {
        int row = idx >> 5, k4 = idx & 31;
        hi4[row*33 + k4] = ((const float4*)(g_h + (base + i0 + row)*Dd))[k4];
        hj4[row*33 + k4] = ((const float4*)(g_h + (base + j0 + row)*Dd))[k4];
        ri4[row*33 + k4] = ((const float4*)(g_r + (base + i0 + row)*Dd))[k4];
        rj4[row*33 + k4] = ((const float4*)(g_r + (base + j0 + row)*Dd))[k4];
    }
    if (tid < 16) { ssi[tid] = g_s[base + i0 + tid]; ssj[tid] = g_s[base + j0 + tid]; }
    if (tid >= 64 && tid < 96)  w2s4[tid - 64] = ((const float4*)att_w2)[tid - 64];
    if (tid >= 96 && tid < 128) b1s4[tid - 96] = ((const float4*)att_b1)[tid - 96];
    int ti = tid >> 4, tj = tid & 15;
    float mval = mask[(base + i0 + ti)*Nn + j0 + tj];
    float b2v  = __ldg(att_b2);
    __syncthreads();

    // gram <h_i, h_j>
    float g = 0.f;
    #pragma unroll
    for (int k4 = 0; k4 < 32; k4++) {
        float4 a = hi4[ti*33 + k4];
        float4 c = hj4[tj*33 + k4];
        g = fmaf(a.x, c.x, fmaf(a.y, c.y, fmaf(a.z, c.z, fmaf(a.w, c.w, g))));
    }
    float si = ssi[ti], sj = ssj[tj];

    float A   = 1.0f - 2.0f*g + sj;
    float Bc  = 1.0f - si;
    float den = fmaxf(1.0f - 2.0f*g + si*sj, 1e-15f);
    float p = -A / den, q = Bc / den;
    float sn2 = fmaf(p*p, si, fmaf(2.0f*p*q, g, q*q*sj));
    float sn  = fmaxf(sqrtf(fmaxf(sn2, 0.0f)), 1e-15f);
    float fac = fmaxf(1.0f - si, 1e-15f) * artanhf_c(sn) / sn;
    float U = fac * p, V = fac * q;

    // attention logit: e = sum_k w2[k]*silu(b1[k]+U*r_i[k]+V*r_j[k]); silu via tanh.approx
    float e = 0.f;
    #pragma unroll
    for (int k4 = 0; k4 < 32; k4++) {
        float4 rv = ri4[ti*33 + k4];
        float4 sv = rj4[tj*33 + k4];
        float4 bv = b1s4[k4];
        float4 wv = w2s4[k4];
        {
            float a = fmaf(U, rv.x, fmaf(V, sv.x, bv.x));
            float s = 0.5f * fmaf(a, tanhap(0.5f*a), a);
            e = fmaf(wv.x, s, e);
        }
        {
            float a = fmaf(U, rv.y, fmaf(V, sv.y, bv.y));
            float s = 0.5f * fmaf(a, tanhap(0.5f*a), a);
            e = fmaf(wv.y, s, e);
        }
        {
            float a = fmaf(U, rv.z, fmaf(V, sv.z, bv.z));
            float s = 0.5f * fmaf(a, tanhap(0.5f*a), a);
            e = fmaf(wv.z, s, e);
        }
        {
            float a = fmaf(U, rv.w, fmaf(V, sv.w, bv.w));
            float s = 0.5f * fmaf(a, tanhap(0.5f*a), a);
            e = fmaf(wv.w, s, e);
        }
    }
    float w = __fdividef(1.0f, 1.0f + __expf(-(e + b2v))) * mval;

    g_m2[(base + i0 + ti)*Nn + j0 + tj] = w * V;

    redsm[ti*17 + tj] = w * U;
    __syncthreads();
    if (tj == 0) {
        float s = 0.f;
        #pragma unroll
        for (int x2i = 0; x2i < 16; x2i++) s += redsm[ti*17 + x2i];
        g_sup[(base + i0 + ti)*16 + blockIdx.x] = s;
    }
}

// ======================= K4: j-split partials of M2 @ H =======================
__global__ void k_agg() {
    __shared__ float4 ms4[16*16];
    int b  = blockIdx.z;
    int js = blockIdx.y;
    int i0 = blockIdx.x * 16;
    int base = b * Nn;
    int j0 = js * 64;
    int tid = threadIdx.x;  // 128 = channel k

    for (int idx = tid; idx < 256; idx += 128) {
        int r = idx >> 4, k = idx & 15;
        ms4[r*16 + k] = ((const float4*)(g_m2 + (base + i0 + r)*Nn + j0))[k];
    }
    __syncthreads();
    float acc[16];
    #pragma unroll
    for (int ti = 0; ti < 16; ti++) acc[ti] = 0.f;
    #pragma unroll 4
    for (int j4 = 0; j4 < 16; j4++) {
        const float* hp = g_h + (base + j0 + j4*4)*Dd + tid;
        float h0 = hp[0], h1 = hp[Dd], h2 = hp[2*Dd], h3 = hp[3*Dd];
        #pragma unroll
        for (int ti = 0; ti < 16; ti++) {
            float4 m = ms4[ti*16 + j4];
            acc[ti] = fmaf(m.x, h0, fmaf(m.y, h1, fmaf(m.z, h2, fmaf(m.w, h3, acc[ti]))));
        }
    }
    #pragma unroll
    for (int ti = 0; ti < 16; ti++)
        g_part[(js*NODES + base + i0 + ti)*Dd + tid] = acc[ti];
}

// ======================= K5: combine + node MLP + expmap + HypAct (warp-per-node) =======================
__global__ void k_mlp(const float* __restrict__ mlp_w1, const float* __restrict__ mlp_b1,
                      const float* __restrict__ mlp_w2, const float* __restrict__ mlp_b2,
                      float* __restrict__ out) {
    extern __shared__ float4 dsm4[];
    float4* W1s4 = dsm4;              // 128*WP
    float4* W2s4 = dsm4 + 128*WP;     // 128*WP
    float4* vs4  = W2s4 + 128*WP;     // 8*32
    float* W1s = (float*)W1s4;
    float* W2s = (float*)W2s4;
    int t = threadIdx.x, wid = t >> 5, lane = t & 31;

    for (int idx = t; idx < Dd*Dd; idx += 256) {
        int c = idx >> 7, m = idx & 127;
        W1s[m*132 + c] = mlp_w1[c*(2*Dd) + Dd + m];
        W2s[m*132 + c] = mlp_w2[c*Dd + m];
    }
    float4 b1v = ((const float4*)mlp_b1)[lane];
    float4 b2v = ((const float4*)mlp_b2)[lane];
    __syncthreads();

    int node = blockIdx.x * 8 + wid;
    float4* vw = vs4 + wid*32;

    // combine j-split partials + diagonal term
    float4 sv = make_float4(0.f,0.f,0.f,0.f);
    #pragma unroll
    for (int js = 0; js < 4; js++) {
        float4 p = ((const float4*)(g_part + (js*NODES + node)*Dd))[lane];
        sv.x += p.x; sv.y += p.y; sv.z += p.z; sv.w += p.w;
    }
    float su = 0.f;
    #pragma unroll
    for (int jt = 0; jt < 16; jt++) su += g_sup[node*16 + jt];
    float4 h4 = ((const float4*)(g_h + node*Dd))[lane];
    float4 sup = make_float4(fmaf(su, h4.x, sv.x), fmaf(su, h4.y, sv.y),
                             fmaf(su, h4.z, sv.z), fmaf(su, h4.w, sv.w));
    vw[lane] = sup;
    __syncwarp();
    float4 a1 = matvec128(W1s4, vw, lane);
    a1.x += b1v.x; a1.y += b1v.y; a1.z += b1v.z; a1.w += b1v.w;
    // silu (accurate)
    float4 sa;
    sa.x = a1.x / (1.0f + __expf(-a1.x));
    sa.y = a1.y / (1.0f + __expf(-a1.y));
    sa.z = a1.z / (1.0f + __expf(-a1.z));
    sa.w = a1.w / (1.0f + __expf(-a1.w));
    __syncwarp();               // matvec1 reads done before overwrite
    vw[lane] = sa;
    __syncwarp();
    float4 o = matvec128(W2s4, vw, lane);
    o.x += b2v.x; o.y += b2v.y; o.z += b2v.z; o.w += b2v.w;

    float si = g_s[node];
    // expmap(o, h)
    float un2 = warpSum(dot4(o, o));
    float un  = fmaxf(sqrtf(un2), 1e-15f);
    float lam = 2.0f / fmaxf(1.0f - si, 1e-15f);
    float tt  = tanhf(0.5f * lam * un);
    float sc  = tt / un;
    float4 sec = make_float4(sc*o.x, sc*o.y, sc*o.z, sc*o.w);
    float y2  = tt * tt;
    // mobius_add(h, sec)
    float xy = warpSum(dot4(h4, sec));
    float A   = 1.0f + 2.0f*xy + y2;
    float Bc  = 1.0f - si;
    float den = fmaxf(1.0f + 2.0f*xy + si*y2, 1e-15f);
    float id  = 1.0f/den;
    float4 ov = make_float4((A*h4.x + Bc*sec.x)*id, (A*h4.y + Bc*sec.y)*id,
                            (A*h4.z + Bc*sec.z)*id, (A*h4.w + Bc*sec.w)*id);
    // proj
    float on2 = warpSum(dot4(ov, ov));
    float on  = fmaxf(sqrtf(on2), 1e-15f);
    float pn2;
    if (on > MAXN) { float s = MAXN/on; ov.x*=s; ov.y*=s; ov.z*=s; ov.w*=s; pn2 = MAXN*MAXN; }
    else           { pn2 = on2; }
    // HypAct: silu(logmap0(ov)) -> expmap0 -> proj
    float pn  = fmaxf(sqrtf(pn2), 1e-15f);
    float lsc = artanhf_c(pn) / pn;
    float4 xt = make_float4(lsc*ov.x, lsc*ov.y, lsc*ov.z, lsc*ov.w);
    xt.x = xt.x / (1.0f + __expf(-xt.x));
    xt.y = xt.y / (1.0f + __expf(-xt.y));
    xt.z = xt.z / (1.0f + __expf(-xt.z));
    xt.w = xt.w / (1.0f + __expf(-xt.w));
    float un3 = warpSum(dot4(xt, xt));
    float u3n = fmaxf(sqrtf(un3), 1e-15f);
    float t3  = tanhf(u3n);
    float rsc = t3 / u3n;
    float4 rv = make_float4(rsc*xt.x, rsc*xt.y, rsc*xt.z, rsc*xt.w);
    float rn  = fmaxf(fabsf(t3), 1e-15f);
    if (rn > MAXN) { float s = MAXN/rn; rv.x*=s; rv.y*=s; rv.z*=s; rv.w*=s; }
    ((float4*)(out + node*Dd))[lane] = rv;
}

// ======================= launch =======================
extern "C" void kernel_launch(void* const* d_in, const int* in_sizes, int n_in,
                              void* d_out, int out_size) {
    const float* x      = (const float*)d_in[0];
    const float* mask   = (const float*)d_in[1];
    const float* W      = (const float*)d_in[2];
    const float* b_lin  = (const float*)d_in[3];
    const float* att_w1 = (const float*)d_in[4];
    const float* att_b1 = (const float*)d_in[5];
    const float* att_w2 = (const float*)d_in[6];
    const float* att_b2 = (const float*)d_in[7];
    const float* mlp_w1 = (const float*)d_in[8];
    const float* mlp_b1 = (const float*)d_in[9];
    const float* mlp_w2 = (const float*)d_in[10];
    const float* mlp_b2 = (const float*)d_in[11];
    float* out = (float*)d_out;

    const int smemN = (2*128*WP + 8*32) * (int)sizeof(float4);   // 139,264 B
    cudaFuncSetAttribute(k_hyplinear, cudaFuncAttributeMaxDynamicSharedMemorySize, smemN);
    cudaFuncSetAttribute(k_mlp,       cudaFuncAttributeMaxDynamicSharedMemorySize, smemN);

    k_hyplinear<<<NODES/8, 256, smemN>>>(x, W, b_lin, att_w1);
    dim3 g3(Nn/16, Nn/16, Bb);
    k_pair<<<g3, 256>>>(mask, att_b1, att_w2, att_b2);
    dim3 g4(Nn/16, 4, Bb);
    k_agg<<<g4, 128>>>();
    k_mlp<<<NODES/8, 256, smemN>>>(mlp_w1, mlp_b1, mlp_w2, mlp_b2, out);
}